// round 7
// baseline (speedup 1.0000x reference)
#include <cuda_runtime.h>
#include <cuda_bf16.h>

#define SDIM 1024
#define BATCH 256
#define FPSCALE 4294967296.0  // 2^32 fixed-point quantum for deterministic atomics
#define FULLM 0xFFFFFFFFu

// Grid-reduction scratch; last block resets after producing the output so every
// graph replay sees clean state (integer atomics: exact & commutative).
__device__ unsigned long long g_sum_acc = 0ULL;
__device__ unsigned long long g_cnt_acc = 0ULL;
__device__ unsigned int       g_done    = 0u;

__device__ __forceinline__ float window_term(int p0, int p1, float y_hat,
                                             long long S0, long long S1, long long Q)
{
    // sq = sum_{b'} ||pos - gt[b']||^2 (exact closed form)
    const long long sq =
        (long long)BATCH * ((long long)p0 * p0 + (long long)p1 * p1)
        - 2LL * ((long long)p0 * S0 + (long long)p1 * S1) + Q;
    const float y = expf(-(float)sq * 0.2f);
    const float d = y_hat - y;
    if (y == 1.0f) {
        return -logf(y_hat) * d * d;
    } else {
        const float om  = 1.0f - y;
        const float om2 = om * om;
        return -logf(1.0f - y_hat) * om2 * om2 * d * d;
    }
}

__global__ __launch_bounds__(64, 8)
void loss_kernel(const float* __restrict__ yp,
                 const int*   __restrict__ gt,
                 float*       __restrict__ out)
{
    const int b    = blockIdx.x;     // one block per batch element
    const int lane = threadIdx.x & 31;
    const int warp = threadIdx.x >> 5;

    __shared__ long long sS0, sS1, sQ;

    // ---- warp 0: S0/S1/Q over all 256 gt pairs (int4 loads + shuffles) ----
    // Runs in parallel with warp 1's dependent gather chain -> off critical path.
    if (warp == 0) {
        const int4* g4 = (const int4*)gt;   // 256 pairs = 128 int4
        long long s0 = 0, s1 = 0, q = 0;
#pragma unroll
        for (int i = 0; i < 4; i++) {
            const int4 v = g4[lane + 32 * i];
            s0 += (long long)v.x + v.z;
            s1 += (long long)v.y + v.w;
            q  += (long long)v.x * v.x + (long long)v.y * v.y
                + (long long)v.z * v.z + (long long)v.w * v.w;
        }
#pragma unroll
        for (int o = 16; o; o >>= 1) {
            s0 += __shfl_down_sync(FULLM, s0, o);
            s1 += __shfl_down_sync(FULLM, s1, o);
            q  += __shfl_down_sync(FULLM, q,  o);
        }
        if (lane == 0) { sS0 = s0; sS1 = s1; sQ = q; }
    }

    // ---- warp 1: issue the gather chain immediately (gt[b] -> yp loads) ----
    int  p0a = 0, p1a = 0, p0b = 0, p1b = 0;
    bool v1 = false, v2 = false;
    float yh1 = 0.5f, yh2 = 0.5f;

    if (warp == 1) {
        const int2 g = *(const int2*)(gt + 2 * b);
        const size_t base = (size_t)b * (SDIM * SDIM);
        {   // window element k = lane (0..31, always < 36)
            p0a = g.x + lane / 6 - 3;
            p1a = g.y + lane % 6 - 3;
            v1  = (p0a >= 0) & (p0a < SDIM) & (p1a >= 0) & (p1a < SDIM);
            if (v1) yh1 = yp[base + (size_t)p0a * SDIM + p1a];
        }
        {   // window element k = lane + 32 (only lanes 0..3)
            const int k = lane + 32;
            p0b = g.x + k / 6 - 3;
            p1b = g.y + k % 6 - 3;
            v2  = (k < 36) & (p0b >= 0) & (p0b < SDIM) & (p1b >= 0) & (p1b < SDIM);
            if (v2) yh2 = yp[base + (size_t)p0b * SDIM + p1b];
        }
    }

    __syncthreads();   // the ONLY block barrier: publishes sS0/sS1/sQ

    if (warp == 1) {
        const long long S0 = sS0, S1 = sS1, Q = sQ;

        double term = 0.0;
        int    cnt  = 0;
        if (v1) { term += (double)window_term(p0a, p1a, yh1, S0, S1, Q); cnt++; }
        if (v2) { term += (double)window_term(p0b, p1b, yh2, S0, S1, Q); cnt++; }

        // warp shuffle reduction (deterministic order)
#pragma unroll
        for (int o = 16; o; o >>= 1) {
            term += __shfl_down_sync(FULLM, term, o);
            cnt  += __shfl_down_sync(FULLM, cnt,  o);
        }

        if (lane == 0) {
            const unsigned long long q =
                (unsigned long long)(term * FPSCALE + 0.5);
            atomicAdd(&g_sum_acc, q);
            atomicAdd(&g_cnt_acc, (unsigned long long)cnt);
            __threadfence();
            const unsigned int done = atomicAdd(&g_done, 1u);
            if (done == gridDim.x - 1) {
                const unsigned long long sum_q = atomicAdd(&g_sum_acc, 0ULL);
                const unsigned long long c     = atomicAdd(&g_cnt_acc, 0ULL);
                out[0] = (float)(((double)sum_q / FPSCALE) / (double)c);
                // reset for next graph replay
                g_sum_acc = 0ULL;
                g_cnt_acc = 0ULL;
                g_done    = 0u;
            }
        }
    }
}

extern "C" void kernel_launch(void* const* d_in, const int* in_sizes, int n_in,
                              void* d_out, int out_size)
{
    const float* y_predict = (const float*)d_in[0];
    const int*   gt_pos    = (const int*)d_in[1];
    float*       out       = (float*)d_out;
    loss_kernel<<<BATCH, 64>>>(y_predict, gt_pos, out);
}

// round 8
// speedup vs baseline: 1.1296x; 1.1296x over previous
#include <cuda_runtime.h>
#include <cuda_bf16.h>

#define SDIM 1024
#define BATCH 256
#define FULLM 0xFFFFFFFFu

// Single packed accumulator:
//   bits [63:23] : loss sum, fixed point, quantum 2^-24  (sum < 2^16 -> 41 bits)
//   bits [22: 9] : valid count                            (<= 9216  -> 14 bits)
//   bits [ 8: 0] : block arrival count                    (= 256    ->  9 bits)
// Field totals cannot carry across boundaries. One atomicAdd accumulates AND
// signals arrival; the returned old value lets the last block finish inline.
// Last block resets to 0 for the next graph replay (kernel-boundary ordering
// makes the reset visible to the next launch).
#define SUM_SHIFT 23
#define CNT_SHIFT 9
#define SUM_Q     16777216.0   // 2^24

__device__ unsigned long long g_acc = 0ULL;

__device__ __forceinline__ float window_term(int p0, int p1, float y_hat,
                                             long long S0, long long S1, long long Q)
{
    // sq = sum_{b'} ||pos - gt[b']||^2 (exact closed form)
    const long long sq =
        (long long)BATCH * ((long long)p0 * p0 + (long long)p1 * p1)
        - 2LL * ((long long)p0 * S0 + (long long)p1 * S1) + Q;
    const float y = expf(-(float)sq * 0.2f);
    const float d = y_hat - y;
    if (y == 1.0f) {
        return -logf(y_hat) * d * d;
    } else {
        const float om  = 1.0f - y;
        const float om2 = om * om;
        return -logf(1.0f - y_hat) * om2 * om2 * d * d;
    }
}

__global__ __launch_bounds__(64)
void loss_kernel(const float* __restrict__ yp,
                 const int*   __restrict__ gt,
                 float*       __restrict__ out)
{
    const int b    = blockIdx.x;     // one block per batch element
    const int lane = threadIdx.x & 31;
    const int warp = threadIdx.x >> 5;

    __shared__ long long sS0, sS1, sQ;

    // ---- warp 0: S0/S1/Q over all 256 gt pairs (int4 loads + shuffles) ----
    // Runs concurrently with warp 1's dependent gather chain.
    if (warp == 0) {
        const int4* g4 = (const int4*)gt;   // 256 pairs = 128 int4
        long long s0 = 0, s1 = 0, q = 0;
#pragma unroll
        for (int i = 0; i < 4; i++) {
            const int4 v = __ldg(&g4[lane + 32 * i]);
            s0 += (long long)v.x + v.z;
            s1 += (long long)v.y + v.w;
            q  += (long long)v.x * v.x + (long long)v.y * v.y
                + (long long)v.z * v.z + (long long)v.w * v.w;
        }
#pragma unroll
        for (int o = 16; o; o >>= 1) {
            s0 += __shfl_down_sync(FULLM, s0, o);
            s1 += __shfl_down_sync(FULLM, s1, o);
            q  += __shfl_down_sync(FULLM, q,  o);
        }
        if (lane == 0) { sS0 = s0; sS1 = s1; sQ = q; }
    }

    // ---- warp 1: issue the gather chain immediately (gt[b] -> yp loads) ----
    int  p0a = 0, p1a = 0, p0b = 0, p1b = 0;
    bool v1 = false, v2 = false;
    float yh1 = 0.5f, yh2 = 0.5f;

    if (warp == 1) {
        const int2 g = __ldg((const int2*)(gt + 2 * b));
        const size_t base = (size_t)b * (SDIM * SDIM);
        {   // window element k = lane (0..31)
            p0a = g.x + lane / 6 - 3;
            p1a = g.y + lane % 6 - 3;
            v1  = (p0a >= 0) & (p0a < SDIM) & (p1a >= 0) & (p1a < SDIM);
            if (v1) yh1 = __ldg(&yp[base + (size_t)p0a * SDIM + p1a]);
        }
        {   // window element k = lane + 32 (lanes 0..3 only)
            const int k = lane + 32;
            p0b = g.x + k / 6 - 3;
            p1b = g.y + k % 6 - 3;
            v2  = (k < 36) & (p0b >= 0) & (p0b < SDIM) & (p1b >= 0) & (p1b < SDIM);
            if (v2) yh2 = __ldg(&yp[base + (size_t)p0b * SDIM + p1b]);
        }
    }

    __syncthreads();   // only barrier: publishes sS0/sS1/sQ

    if (warp == 1) {
        const long long S0 = sS0, S1 = sS1, Q = sQ;

        double term = 0.0;
        int    cnt  = 0;
        if (v1) { term += (double)window_term(p0a, p1a, yh1, S0, S1, Q); cnt++; }
        if (v2) { term += (double)window_term(p0b, p1b, yh2, S0, S1, Q); cnt++; }

#pragma unroll
        for (int o = 16; o; o >>= 1) {
            term += __shfl_down_sync(FULLM, term, o);
            cnt  += __shfl_down_sync(FULLM, cnt,  o);
        }

        if (lane == 0) {
            // quantize block sum (terms are >= 0, total < 2^16)
            const unsigned long long sum_q =
                (unsigned long long)(term * SUM_Q + 0.5);
            const unsigned long long mine =
                (sum_q << SUM_SHIFT) |
                ((unsigned long long)cnt << CNT_SHIFT) | 1ULL;

            const unsigned long long old = atomicAdd(&g_acc, mine);

            if ((old & 0x1FFULL) == (unsigned long long)(gridDim.x - 1)) {
                // I'm the last arrival; old + mine is the exact final total.
                const unsigned long long fin = old + mine;
                const unsigned long long fsum = fin >> SUM_SHIFT;
                const unsigned long long fcnt = (fin >> CNT_SHIFT) & 0x3FFFULL;
                out[0] = (float)(((double)fsum / SUM_Q) / (double)fcnt);
                g_acc = 0ULL;   // reset for next graph replay
            }
        }
    }
}

extern "C" void kernel_launch(void* const* d_in, const int* in_sizes, int n_in,
                              void* d_out, int out_size)
{
    const float* y_predict = (const float*)d_in[0];
    const int*   gt_pos    = (const int*)d_in[1];
    float*       out       = (float*)d_out;
    loss_kernel<<<BATCH, 64>>>(y_predict, gt_pos, out);
}

// round 11
// speedup vs baseline: 1.3413x; 1.1875x over previous
#include <cuda_runtime.h>
#include <cuda_bf16.h>

#define SDIM  1024
#define BATCH 256
#define NBLK  32
#define BPB   8          // batches per block
#define TPB   320        // warps 0..8 = 288 term threads, warp 9 = S-sum warp
#define FULLM 0xFFFFFFFFu

// Single packed accumulator:
//   bits [63:23] : loss sum, fixed point, quantum 2^-24  (sum < 2^17 -> fits 41b)
//   bits [22: 9] : valid count                            (<= 9216  -> 14 bits)
//   bits [ 8: 0] : block arrival count                    (= 32     ->  9 bits)
// Field totals cannot carry across boundaries. One atomicAdd per block both
// accumulates and signals arrival; the returned old value lets the last block
// finalize inline. Last block resets to 0 for the next graph replay.
#define SUM_SHIFT 23
#define CNT_SHIFT 9
#define SUM_QF    16777216.0f   // 2^24
#define SUM_QD    16777216.0    // 2^24

__device__ unsigned long long g_acc = 0ULL;

__global__ __launch_bounds__(TPB)
void loss_kernel(const float* __restrict__ yp,
                 const int*   __restrict__ gt,
                 float*       __restrict__ out)
{
    const int t    = threadIdx.x;
    const int lane = t & 31;
    const int warp = t >> 5;

    __shared__ long long sS0, sS1, sQ;
    __shared__ unsigned long long spart[9];

    int   p0 = 0, p1 = 0;
    bool  valid = false;
    float yh = 0.5f;

    if (warp < 9) {
        // ---- term threads: one (batch, window-element) pair each ----
        const int lb = t / 36;            // 0..7
        const int k  = t - lb * 36;       // 0..35
        const int b  = blockIdx.x * BPB + lb;
        const int2 g = __ldg((const int2*)(gt + 2 * b));
        p0 = g.x + k / 6 - 3;
        p1 = g.y + k % 6 - 3;
        valid = (p0 >= 0) & (p0 < SDIM) & (p1 >= 0) & (p1 < SDIM);
        if (valid)
            yh = __ldg(&yp[(size_t)b * (SDIM * SDIM) + (size_t)p0 * SDIM + p1]);
    } else {
        // ---- warp 9: S0/S1/Q over all 256 gt pairs, concurrent with gathers ----
        const int4* g4 = (const int4*)gt;     // 256 pairs = 128 int4
        long long s0 = 0, s1 = 0, q = 0;
#pragma unroll
        for (int i = 0; i < 4; i++) {
            const int4 v = __ldg(&g4[lane + 32 * i]);
            s0 += (long long)v.x + v.z;
            s1 += (long long)v.y + v.w;
            q  += (long long)v.x * v.x + (long long)v.y * v.y
                + (long long)v.z * v.z + (long long)v.w * v.w;
        }
#pragma unroll
        for (int o = 16; o; o >>= 1) {
            s0 += __shfl_down_sync(FULLM, s0, o);
            s1 += __shfl_down_sync(FULLM, s1, o);
            q  += __shfl_down_sync(FULLM, q,  o);
        }
        if (lane == 0) { sS0 = s0; sS1 = s1; sQ = q; }
    }

    __syncthreads();   // publishes sS0/sS1/sQ

    if (warp < 9) {
        unsigned long long packed = 0ULL;
        if (valid) {
            const long long S0 = sS0, S1 = sS1, Q = sQ;
            // sq = sum_{b'} ||pos - gt[b']||^2 (exact closed form)
            const long long sq =
                (long long)BATCH * ((long long)p0 * p0 + (long long)p1 * p1)
                - 2LL * ((long long)p0 * S0 + (long long)p1 * S1) + Q;
            const float y = expf(-(float)sq * 0.2f);
            const float d = yh - y;
            float tm;
            if (y == 1.0f) {
                tm = -logf(yh) * d * d;
            } else {
                const float om  = 1.0f - y;
                const float om2 = om * om;
                tm = -logf(1.0f - yh) * om2 * om2 * d * d;
            }
            // per-thread fixed-point quantization (tm >= 0, < 8)
            packed = ((unsigned long long)(tm * SUM_QF + 0.5f) << SUM_SHIFT)
                   | (1ULL << CNT_SHIFT);
        }

        // single u64 shuffle chain carries sum + count together
#pragma unroll
        for (int o = 16; o; o >>= 1)
            packed += __shfl_down_sync(FULLM, packed, o);
        if (lane == 0) spart[warp] = packed;
    }

    __syncthreads();

    if (warp == 0) {
        unsigned long long v = (lane < 9) ? spart[lane] : 0ULL;
#pragma unroll
        for (int o = 8; o; o >>= 1)
            v += __shfl_down_sync(FULLM, v, o);

        if (lane == 0) {
            const unsigned long long mine = v | 1ULL;   // +1 arrival
            const unsigned long long old  = atomicAdd(&g_acc, mine);
            if ((old & 0x1FFULL) == (unsigned long long)(NBLK - 1)) {
                const unsigned long long fin  = old + mine;
                const unsigned long long fsum = fin >> SUM_SHIFT;
                const unsigned long long fcnt = (fin >> CNT_SHIFT) & 0x3FFFULL;
                out[0] = (float)(((double)fsum / SUM_QD) / (double)fcnt);
                g_acc = 0ULL;   // reset for next graph replay
            }
        }
    }
}

extern "C" void kernel_launch(void* const* d_in, const int* in_sizes, int n_in,
                              void* d_out, int out_size)
{
    const float* y_predict = (const float*)d_in[0];
    const int*   gt_pos    = (const int*)d_in[1];
    float*       out       = (float*)d_out;
    loss_kernel<<<NBLK, TPB>>>(y_predict, gt_pos, out);
}